// round 11
// baseline (speedup 1.0000x reference)
#include <cuda_runtime.h>
#include <cstdint>

#define BATCH    16384
#define NFIELDS  50
#define DIM      64
#define L1DIM    128
#define L2DIM    64
#define ROWS     32      // batch rows per block
#define THREADS  256     // 8 warps, 4 rows per warp
#define RING     8       // staging slots per warp, 512 B each
#define LOOKAHEAD 6      // cp.async units in flight per warp

// shared memory:
//   [0, 32KB)   : cp.async staging, 8 warps x RING x 512B
//                 (overlaid by sFM [ROWS x 64] = 8KB after gather,
//                  then sH2 [ROWS x 64] overlays sFM after h1)
//   [32K, 48K)  : sH1 [ROWS x 128] = 16KB
#define SMEM_BYTES (32768 + 16384)

__device__ __forceinline__ void cp_async16(uint32_t dst, const void* src) {
    asm volatile("cp.async.cg.shared.global [%0], [%1], 16;\n"
                 :: "r"(dst), "l"(src));
}
__device__ __forceinline__ void cp_commit() {
    asm volatile("cp.async.commit_group;\n");
}
__device__ __forceinline__ void cp_wait5() {
    asm volatile("cp.async.wait_group 5;\n" ::: "memory");
}

__global__ __launch_bounds__(THREADS, 4)
void nfm_fused_kernel(const int*   __restrict__ features,
                      const float* __restrict__ emb,
                      const float* __restrict__ bias_table,
                      const float* __restrict__ w_bias,
                      const float* __restrict__ W1,
                      const float* __restrict__ b1,
                      const float* __restrict__ W2,
                      const float* __restrict__ b2,
                      const float* __restrict__ Wp,
                      const float* __restrict__ bp,
                      float*       __restrict__ out)
{
    extern __shared__ float sm[];
    float* sFM = sm;                 // 8KB, overlays staging after gather
    float* sH1 = sm + 32768 / 4;     // 16KB
    float* sH2 = sm;                 // overlays sFM after h1

    const int tid  = threadIdx.x;
    const int lane = tid & 31;
    const int wid  = tid >> 5;
    const int l16  = lane & 15;
    const int row0 = blockIdx.x * ROWS;
    const int r0   = wid * 4;                 // this warp's first local row

    // per-warp staging base (shared address space)
    const uint32_t stageAddr =
        (uint32_t)__cvta_generic_to_shared(sm) + wid * (RING * 512);
    const char* stageGen = reinterpret_cast<const char*>(sm) + wid * (RING * 512);

    // ---- gather: cp.async pipeline, 100 units (2 pairs x 50 fields) --------
    // unit u: pair p = u&1, field f = u>>1.
    // lanes 0-15 fetch row (r0+2p), lanes 16-31 fetch row (r0+2p+1),
    // each lane 16 bytes -> one 512B row-pair per unit.
    float bs0 = 0.f, bs1 = 0.f, bs2 = 0.f, bs3 = 0.f;   // uniform row biases

    auto issue_unit = [&](int u) {
        const int p  = u & 1;
        const int f  = u >> 1;
        const long base = (long)(row0 + r0 + 2 * p) * NFIELDS + f;
        const int iA = __ldg(features + base);             // uniform
        const int iB = __ldg(features + base + NFIELDS);   // uniform
        if (p == 0) { bs0 += __ldg(bias_table + iA); bs1 += __ldg(bias_table + iB); }
        else        { bs2 += __ldg(bias_table + iA); bs3 += __ldg(bias_table + iB); }
        const int idx = (lane < 16) ? iA : iB;
        cp_async16(stageAddr + ((u & (RING - 1)) << 9) + lane * 16,
                   emb + (long)idx * DIM + l16 * 4);
        cp_commit();
    };

    // prologue: fill the pipeline
    #pragma unroll
    for (int u = 0; u < LOOKAHEAD; ++u) issue_unit(u);

    float4 s0  = make_float4(0.f, 0.f, 0.f, 0.f);
    float4 sq0 = make_float4(0.f, 0.f, 0.f, 0.f);
    float4 s1  = make_float4(0.f, 0.f, 0.f, 0.f);
    float4 sq1 = make_float4(0.f, 0.f, 0.f, 0.f);

    #pragma unroll 4
    for (int u = 0; u < 2 * NFIELDS; ++u) {
        if (u + LOOKAHEAD < 2 * NFIELDS) issue_unit(u + LOOKAHEAD);
        else                             cp_commit();      // keep group count
        cp_wait5();                                        // unit u complete
        const float4 v = *reinterpret_cast<const float4*>(
                             stageGen + ((u & (RING - 1)) << 9) + lane * 16);
        if ((u & 1) == 0) {
            s0.x  += v.x;       s0.y  += v.y;       s0.z  += v.z;       s0.w  += v.w;
            sq0.x += v.x * v.x; sq0.y += v.y * v.y; sq0.z += v.z * v.z; sq0.w += v.w * v.w;
        } else {
            s1.x  += v.x;       s1.y  += v.y;       s1.z  += v.z;       s1.w  += v.w;
            sq1.x += v.x * v.x; sq1.y += v.y * v.y; sq1.z += v.z * v.z; sq1.w += v.w * v.w;
        }
    }

    float4 fm0, fm1;
    fm0.x = 0.5f * (s0.x * s0.x - sq0.x);
    fm0.y = 0.5f * (s0.y * s0.y - sq0.y);
    fm0.z = 0.5f * (s0.z * s0.z - sq0.z);
    fm0.w = 0.5f * (s0.w * s0.w - sq0.w);
    fm1.x = 0.5f * (s1.x * s1.x - sq1.x);
    fm1.y = 0.5f * (s1.y * s1.y - sq1.y);
    fm1.z = 0.5f * (s1.z * s1.z - sq1.z);
    fm1.w = 0.5f * (s1.w * s1.w - sq1.w);

    __syncthreads();   // ALL staging consumed block-wide -> safe to overlay sFM

    {
        const int half = (lane < 16) ? 0 : 1;
        *reinterpret_cast<float4*>(sFM + (r0 + half)     * DIM + l16 * 4) = fm0;
        *reinterpret_cast<float4*>(sFM + (r0 + 2 + half) * DIM + l16 * 4) = fm1;
    }
    __syncthreads();

    // ---- h1 = relu(FM @ W1 + b1): 4 rows/warp, float4 weights (as R8) ------
    {
        const int c4 = lane * 4;
        const float4 bias1 = __ldg(reinterpret_cast<const float4*>(b1 + c4));
        float acc[4][4];
        #pragma unroll
        for (int i = 0; i < 4; ++i) {
            acc[i][0] = bias1.x; acc[i][1] = bias1.y;
            acc[i][2] = bias1.z; acc[i][3] = bias1.w;
        }
        #pragma unroll
        for (int d = 0; d < DIM; ++d) {
            const float4 w = __ldg(reinterpret_cast<const float4*>(
                                       W1 + d * L1DIM + c4));
            #pragma unroll
            for (int i = 0; i < 4; ++i) {
                const float fv = sFM[(r0 + i) * DIM + d];   // broadcast
                acc[i][0] += fv * w.x;  acc[i][1] += fv * w.y;
                acc[i][2] += fv * w.z;  acc[i][3] += fv * w.w;
            }
        }
        #pragma unroll
        for (int i = 0; i < 4; ++i) {
            float4 r;
            r.x = fmaxf(acc[i][0], 0.f);
            r.y = fmaxf(acc[i][1], 0.f);
            r.z = fmaxf(acc[i][2], 0.f);
            r.w = fmaxf(acc[i][3], 0.f);
            *reinterpret_cast<float4*>(sH1 + (r0 + i) * L1DIM + c4) = r;
        }
    }
    __syncthreads();   // sFM dead; safe to overlay sH2

    // ---- h2 = relu(H1 @ W2 + b2): 4 rows/warp, float2 weights --------------
    {
        const int c2 = lane * 2;
        const float2 bias2 = __ldg(reinterpret_cast<const float2*>(b2 + c2));
        float acc[4][2];
        #pragma unroll
        for (int i = 0; i < 4; ++i) {
            acc[i][0] = bias2.x;
            acc[i][1] = bias2.y;
        }
        #pragma unroll
        for (int d = 0; d < L1DIM; ++d) {
            const float2 w = __ldg(reinterpret_cast<const float2*>(
                                       W2 + d * L2DIM + c2));
            #pragma unroll
            for (int i = 0; i < 4; ++i) {
                const float h = sH1[(r0 + i) * L1DIM + d];  // broadcast
                acc[i][0] += h * w.x;
                acc[i][1] += h * w.y;
            }
        }
        #pragma unroll
        for (int i = 0; i < 4; ++i) {
            float2 r;
            r.x = fmaxf(acc[i][0], 0.f);
            r.y = fmaxf(acc[i][1], 0.f);
            *reinterpret_cast<float2*>(sH2 + (r0 + i) * L2DIM + c2) = r;
        }
    }
    __syncthreads();

    // ---- pred = H2 @ Wp + bp, final sum -------------------------------------
    {
        const float gb  = __ldg(w_bias);
        const float bpv = __ldg(bp);
        const float wp0 = __ldg(Wp + lane);
        const float wp1 = __ldg(Wp + lane + 32);
        const float rowBias[4] = { bs0, bs1, bs2, bs3 };
        #pragma unroll
        for (int i = 0; i < 4; ++i) {
            const int rl = r0 + i;
            float v = sH2[rl * L2DIM + lane]      * wp0
                    + sH2[rl * L2DIM + lane + 32] * wp1;
            #pragma unroll
            for (int o = 16; o; o >>= 1) v += __shfl_down_sync(0xffffffffu, v, o);
            if (lane == 0) out[row0 + rl] = v + bpv + rowBias[i] + gb;
        }
    }
}

extern "C" void kernel_launch(void* const* d_in, const int* in_sizes, int n_in,
                              void* d_out, int out_size)
{
    const int*   features   = (const int*)  d_in[0];
    // d_in[1] = labels (unused, shape-only in reference)
    const float* emb        = (const float*)d_in[2];
    const float* bias_table = (const float*)d_in[3];
    const float* w_bias     = (const float*)d_in[4];
    const float* W1         = (const float*)d_in[5];
    const float* b1         = (const float*)d_in[6];
    const float* W2         = (const float*)d_in[7];
    const float* b2         = (const float*)d_in[8];
    const float* Wp         = (const float*)d_in[9];
    const float* bp         = (const float*)d_in[10];
    float*       out        = (float*)d_out;

    cudaFuncSetAttribute(nfm_fused_kernel,
                         cudaFuncAttributeMaxDynamicSharedMemorySize, SMEM_BYTES);

    nfm_fused_kernel<<<BATCH / ROWS, THREADS, SMEM_BYTES>>>(
        features, emb, bias_table, w_bias, W1, b1, W2, b2, Wp, bp, out);
}

// round 12
// speedup vs baseline: 1.0616x; 1.0616x over previous
#include <cuda_runtime.h>
#include <cstdint>

#define BATCH    16384
#define NFIELDS  50
#define DIM      64
#define L1DIM    128
#define L2DIM    64
#define ROWS     16      // batch rows per block
#define THREADS  256     // 8 warps: gather 2 rows/warp, MLP split rows x col-halves

// dynamic shared layout (floats):
//   sFM : ROWS*64   (reused as sH2 after h1)
//   sH1 : ROWS*128
#define SMEM_FLOATS (ROWS*64 + ROWS*128)

__global__ __launch_bounds__(THREADS, 5)
void nfm_fused_kernel(const int*   __restrict__ features,
                      const float* __restrict__ emb,
                      const float* __restrict__ bias_table,
                      const float* __restrict__ w_bias,
                      const float* __restrict__ W1,
                      const float* __restrict__ b1,
                      const float* __restrict__ W2,
                      const float* __restrict__ b2,
                      const float* __restrict__ Wp,
                      const float* __restrict__ bp,
                      float*       __restrict__ out)
{
    extern __shared__ float sm[];
    float* sFM = sm;               // ROWS*64
    float* sH1 = sm + ROWS * 64;   // ROWS*128
    float* sH2 = sFM;              // overlay (FM dead after h1)

    const int tid  = threadIdx.x;
    const int lane = tid & 31;
    const int wid  = tid >> 5;     // 0..7
    const int row0 = blockIdx.x * ROWS;

    // ---- gather + FM bi-interaction: warp w owns rows 2w, 2w+1 --------------
    // Uniform int2 index loads (no shfl in address path); 2 independent
    // LDG.64 embedding loads per field per row-pair; bias via uniform loads
    // (kept in registers: this warp also writes these rows' outputs).
    float bsA = 0.f, bsB = 0.f;
    {
        const int rA = wid * 2;
        const int rB = rA + 1;
        const int2* frA = reinterpret_cast<const int2*>(
                              features + (long)(row0 + rA) * NFIELDS);
        const int2* frB = reinterpret_cast<const int2*>(
                              features + (long)(row0 + rB) * NFIELDS);

        float2 sA  = make_float2(0.f, 0.f), sqA = make_float2(0.f, 0.f);
        float2 sB  = make_float2(0.f, 0.f), sqB = make_float2(0.f, 0.f);

        #pragma unroll
        for (int f2 = 0; f2 < NFIELDS / 2; ++f2) {        // 25 int2 per row
            const int2 ia2 = __ldg(frA + f2);             // uniform
            const int2 ib2 = __ldg(frB + f2);             // uniform
            const float2 vA0 = *reinterpret_cast<const float2*>(
                                   emb + (long)ia2.x * DIM + lane * 2);
            const float2 vA1 = *reinterpret_cast<const float2*>(
                                   emb + (long)ia2.y * DIM + lane * 2);
            const float2 vB0 = *reinterpret_cast<const float2*>(
                                   emb + (long)ib2.x * DIM + lane * 2);
            const float2 vB1 = *reinterpret_cast<const float2*>(
                                   emb + (long)ib2.y * DIM + lane * 2);
            bsA += __ldg(bias_table + ia2.x) + __ldg(bias_table + ia2.y);
            bsB += __ldg(bias_table + ib2.x) + __ldg(bias_table + ib2.y);
            sA.x  += vA0.x + vA1.x;               sA.y  += vA0.y + vA1.y;
            sqA.x += vA0.x * vA0.x + vA1.x * vA1.x;
            sqA.y += vA0.y * vA0.y + vA1.y * vA1.y;
            sB.x  += vB0.x + vB1.x;               sB.y  += vB0.y + vB1.y;
            sqB.x += vB0.x * vB0.x + vB1.x * vB1.x;
            sqB.y += vB0.y * vB0.y + vB1.y * vB1.y;
        }
        float2 fmA, fmB;
        fmA.x = 0.5f * (sA.x * sA.x - sqA.x);
        fmA.y = 0.5f * (sA.y * sA.y - sqA.y);
        fmB.x = 0.5f * (sB.x * sB.x - sqB.x);
        fmB.y = 0.5f * (sB.y * sB.y - sqB.y);
        *reinterpret_cast<float2*>(sFM + rA * DIM + lane * 2) = fmA;
        *reinterpret_cast<float2*>(sFM + rB * DIM + lane * 2) = fmB;
    }
    __syncthreads();

    // MLP work split: row group g (4 rows) x column half ch
    const int g  = wid & 3;
    const int ch = wid >> 2;
    const int r0 = g * 4;

    // ---- h1 = relu(FM @ W1 + b1): 4 rows x 64 cols per warp ----------------
    // Weight bytes/warp: 64d x 8B x 32 lanes = 16 KB for 4 rows (8 KB/row,
    // same amortization as the best round).
    {
        const int c2 = ch * 64 + lane * 2;     // thread owns cols c2, c2+1
        const float2 bias1 = __ldg(reinterpret_cast<const float2*>(b1 + c2));
        float acc[4][2];
        #pragma unroll
        for (int i = 0; i < 4; ++i) { acc[i][0] = bias1.x; acc[i][1] = bias1.y; }

        #pragma unroll
        for (int d = 0; d < DIM; ++d) {
            const float2 w = __ldg(reinterpret_cast<const float2*>(
                                       W1 + d * L1DIM + c2));
            #pragma unroll
            for (int i = 0; i < 4; ++i) {
                const float fv = sFM[(r0 + i) * DIM + d];   // broadcast
                acc[i][0] += fv * w.x;
                acc[i][1] += fv * w.y;
            }
        }
        #pragma unroll
        for (int i = 0; i < 4; ++i) {
            float2 r;
            r.x = fmaxf(acc[i][0], 0.f);
            r.y = fmaxf(acc[i][1], 0.f);
            *reinterpret_cast<float2*>(sH1 + (r0 + i) * L1DIM + c2) = r;
        }
    }
    __syncthreads();   // sFM dead; safe to overlay sH2

    // ---- h2 = relu(H1 @ W2 + b2): 4 rows x 32 cols per warp ----------------
    {
        const int c = ch * 32 + lane;          // thread owns col c
        const float bias2 = __ldg(b2 + c);
        float acc[4] = { bias2, bias2, bias2, bias2 };

        #pragma unroll
        for (int d = 0; d < L1DIM; ++d) {
            const float w = __ldg(W2 + d * L2DIM + c);
            #pragma unroll
            for (int i = 0; i < 4; ++i)
                acc[i] += sH1[(r0 + i) * L1DIM + d] * w;   // broadcast
        }
        #pragma unroll
        for (int i = 0; i < 4; ++i)
            sH2[(r0 + i) * L2DIM + c] = fmaxf(acc[i], 0.f);
    }
    __syncthreads();

    // ---- pred = H2 @ Wp + bp, final sum: warp w -> rows 2w, 2w+1 ------------
    {
        const float gb  = __ldg(w_bias);
        const float bpv = __ldg(bp);
        const float wp0 = __ldg(Wp + lane);
        const float wp1 = __ldg(Wp + lane + 32);
        const float rowBias[2] = { bsA, bsB };
        #pragma unroll
        for (int i = 0; i < 2; ++i) {
            const int rl = wid * 2 + i;
            float v = sH2[rl * L2DIM + lane]      * wp0
                    + sH2[rl * L2DIM + lane + 32] * wp1;
            #pragma unroll
            for (int o = 16; o; o >>= 1) v += __shfl_down_sync(0xffffffffu, v, o);
            if (lane == 0) out[row0 + rl] = v + bpv + rowBias[i] + gb;
        }
    }
}

extern "C" void kernel_launch(void* const* d_in, const int* in_sizes, int n_in,
                              void* d_out, int out_size)
{
    const int*   features   = (const int*)  d_in[0];
    // d_in[1] = labels (unused, shape-only in reference)
    const float* emb        = (const float*)d_in[2];
    const float* bias_table = (const float*)d_in[3];
    const float* w_bias     = (const float*)d_in[4];
    const float* W1         = (const float*)d_in[5];
    const float* b1         = (const float*)d_in[6];
    const float* W2         = (const float*)d_in[7];
    const float* b2         = (const float*)d_in[8];
    const float* Wp         = (const float*)d_in[9];
    const float* bp         = (const float*)d_in[10];
    float*       out        = (float*)d_out;

    const int smem_bytes = SMEM_FLOATS * sizeof(float);   // 12 KB
    cudaFuncSetAttribute(nfm_fused_kernel,
                         cudaFuncAttributeMaxDynamicSharedMemorySize, smem_bytes);

    nfm_fused_kernel<<<BATCH / ROWS, THREADS, smem_bytes>>>(
        features, emb, bias_table, w_bias, W1, b1, W2, b2, Wp, bp, out);
}

// round 13
// speedup vs baseline: 1.3231x; 1.2463x over previous
#include <cuda_runtime.h>
#include <cstdint>

#define BATCH    16384
#define NFIELDS  50
#define DIM      64
#define L1DIM    128
#define L2DIM    64
#define ROWS     32      // batch rows per block
#define THREADS  256     // 8 warps, 4 rows per warp

// dynamic shared layout (floats):
//   sFM   : ROWS*64   (reused as sH2 after h1 is computed)
//   sH1   : ROWS*128
//   sB1   : 128
//   sB2   : 64
//   sWp   : 64
//   sBias : ROWS
#define SMEM_FLOATS (ROWS*64 + ROWS*128 + 128 + 64 + 64 + ROWS)

__global__ __launch_bounds__(THREADS, 3)   // 84-reg budget: deeper load batching
void nfm_fused_kernel(const int*   __restrict__ features,
                      const float* __restrict__ emb,
                      const float* __restrict__ bias_table,
                      const float* __restrict__ w_bias,
                      const float* __restrict__ W1,
                      const float* __restrict__ b1,
                      const float* __restrict__ W2,
                      const float* __restrict__ b2,
                      const float* __restrict__ Wp,
                      const float* __restrict__ bp,
                      float*       __restrict__ out)
{
    extern __shared__ float sm[];
    float* sFM   = sm;                    // ROWS*64, reused as sH2
    float* sH1   = sFM  + ROWS*64;        // ROWS*128
    float* sB1   = sH1  + ROWS*128;       // 128
    float* sB2   = sB1  + 128;            // 64
    float* sWp   = sB2  + 64;             // 64
    float* sBias = sWp  + 64;             // ROWS
    float* sH2   = sFM;                   // overlay

    const int tid  = threadIdx.x;
    const int lane = tid & 31;
    const int wid  = tid >> 5;

    // ---- stage small params into shared ------------------------------------
    if (tid < 128)       sB1[tid]       = b1[tid];
    else if (tid < 192)  sB2[tid - 128] = b2[tid - 128];
    else                 sWp[tid - 192] = Wp[tid - 192];

    // ---- gather + FM bi-interaction -----------------------------------------
    // warp w owns rows 4w..4w+3 as two pairs. Within a pair: lanes 0-15 = row A,
    // lanes 16-31 = row B, each lane holds 4 dims (float4) -> ONE LDG.128 per
    // field serves both rows. Indices loaded uniformly (int2-vectorized, no
    // shfl in the address path) -> all embedding LDGs independent; extra
    // register headroom lets the compiler keep many in flight.
    const int row0 = blockIdx.x * ROWS;
    const int half = lane >> 4;          // 0 -> row A, 1 -> row B
    const int l16  = lane & 15;

    #pragma unroll
    for (int p = 0; p < 2; ++p) {
        const int rA = wid * 4 + p * 2;
        const int rB = rA + 1;
        const int2* frA = reinterpret_cast<const int2*>(
                              features + (long)(row0 + rA) * NFIELDS);
        const int2* frB = reinterpret_cast<const int2*>(
                              features + (long)(row0 + rB) * NFIELDS);

        float4 s  = make_float4(0.f, 0.f, 0.f, 0.f);
        float4 sq = make_float4(0.f, 0.f, 0.f, 0.f);
        float  bsA = 0.f, bsB = 0.f;

        #pragma unroll
        for (int f2 = 0; f2 < NFIELDS / 2; ++f2) {        // 25 int2 per row
            const int2 ia2 = __ldg(frA + f2);             // uniform
            const int2 ib2 = __ldg(frB + f2);             // uniform
            {
                const int idx = half ? ib2.x : ia2.x;
                const float4 v = *reinterpret_cast<const float4*>(
                                     emb + (long)idx * DIM + l16 * 4);
                bsA += __ldg(bias_table + ia2.x);
                bsB += __ldg(bias_table + ib2.x);
                s.x  += v.x;       s.y  += v.y;       s.z  += v.z;       s.w  += v.w;
                sq.x += v.x * v.x; sq.y += v.y * v.y; sq.z += v.z * v.z; sq.w += v.w * v.w;
            }
            {
                const int idx = half ? ib2.y : ia2.y;
                const float4 v = *reinterpret_cast<const float4*>(
                                     emb + (long)idx * DIM + l16 * 4);
                bsA += __ldg(bias_table + ia2.y);
                bsB += __ldg(bias_table + ib2.y);
                s.x  += v.x;       s.y  += v.y;       s.z  += v.z;       s.w  += v.w;
                sq.x += v.x * v.x; sq.y += v.y * v.y; sq.z += v.z * v.z; sq.w += v.w * v.w;
            }
        }
        float4 fm;
        fm.x = 0.5f * (s.x * s.x - sq.x);
        fm.y = 0.5f * (s.y * s.y - sq.y);
        fm.z = 0.5f * (s.z * s.z - sq.z);
        fm.w = 0.5f * (s.w * s.w - sq.w);
        const int rl = half ? rB : rA;
        *reinterpret_cast<float4*>(sFM + rl * DIM + l16 * 4) = fm;
        if (lane == 0) { sBias[rA] = bsA; sBias[rB] = bsB; }
    }
    __syncthreads();

    // ---- h1 = relu(FM @ W1 + b1)  [ROWS x 128], 4 rows/warp, float4 weights -
    {
        const int c4 = lane * 4;   // thread owns cols c4..c4+3
        const int r0 = wid * 4;    // 4 rows per warp
        float acc[4][4];
        #pragma unroll
        for (int i = 0; i < 4; ++i)
            #pragma unroll
            for (int k = 0; k < 4; ++k) acc[i][k] = sB1[c4 + k];

        #pragma unroll
        for (int d = 0; d < DIM; ++d) {
            const float4 w = __ldg(reinterpret_cast<const float4*>(
                                       W1 + d * L1DIM + c4));
            #pragma unroll
            for (int i = 0; i < 4; ++i) {
                const float fv = sFM[(r0 + i) * DIM + d];   // broadcast
                acc[i][0] += fv * w.x;  acc[i][1] += fv * w.y;
                acc[i][2] += fv * w.z;  acc[i][3] += fv * w.w;
            }
        }
        #pragma unroll
        for (int i = 0; i < 4; ++i) {
            float4 r;
            r.x = fmaxf(acc[i][0], 0.f);
            r.y = fmaxf(acc[i][1], 0.f);
            r.z = fmaxf(acc[i][2], 0.f);
            r.w = fmaxf(acc[i][3], 0.f);
            *reinterpret_cast<float4*>(sH1 + (r0 + i) * L1DIM + c4) = r;
        }
    }
    __syncthreads();   // sFM dead from here; safe to overlay sH2

    // ---- h2 = relu(H1 @ W2 + b2)  [ROWS x 64], 4 rows/warp, float2 weights --
    {
        const int c2 = lane * 2;   // thread owns cols c2, c2+1
        const int r0 = wid * 4;
        float acc[4][2];
        #pragma unroll
        for (int i = 0; i < 4; ++i) {
            acc[i][0] = sB2[c2];
            acc[i][1] = sB2[c2 + 1];
        }
        #pragma unroll
        for (int d = 0; d < L1DIM; ++d) {
            const float2 w = __ldg(reinterpret_cast<const float2*>(
                                       W2 + d * L2DIM + c2));
            #pragma unroll
            for (int i = 0; i < 4; ++i) {
                const float h = sH1[(r0 + i) * L1DIM + d];  // broadcast
                acc[i][0] += h * w.x;
                acc[i][1] += h * w.y;
            }
        }
        #pragma unroll
        for (int i = 0; i < 4; ++i) {
            float2 r;
            r.x = fmaxf(acc[i][0], 0.f);
            r.y = fmaxf(acc[i][1], 0.f);
            *reinterpret_cast<float2*>(sH2 + (r0 + i) * L2DIM + c2) = r;
        }
    }
    __syncthreads();

    // ---- pred = H2 @ Wp + bp, final sum ------------------------------------
    {
        const float gb  = __ldg(w_bias);
        const float bpv = __ldg(bp);
        #pragma unroll
        for (int i = 0; i < 4; ++i) {
            const int rl = wid * 4 + i;
            float v = sH2[rl * L2DIM + lane]      * sWp[lane]
                    + sH2[rl * L2DIM + lane + 32] * sWp[lane + 32];
            #pragma unroll
            for (int o = 16; o; o >>= 1) v += __shfl_down_sync(0xffffffffu, v, o);
            if (lane == 0) out[row0 + rl] = v + bpv + sBias[rl] + gb;
        }
    }
}

extern "C" void kernel_launch(void* const* d_in, const int* in_sizes, int n_in,
                              void* d_out, int out_size)
{
    const int*   features   = (const int*)  d_in[0];
    // d_in[1] = labels (unused, shape-only in reference)
    const float* emb        = (const float*)d_in[2];
    const float* bias_table = (const float*)d_in[3];
    const float* w_bias     = (const float*)d_in[4];
    const float* W1         = (const float*)d_in[5];
    const float* b1         = (const float*)d_in[6];
    const float* W2         = (const float*)d_in[7];
    const float* b2         = (const float*)d_in[8];
    const float* Wp         = (const float*)d_in[9];
    const float* bp         = (const float*)d_in[10];
    float*       out        = (float*)d_out;

    const int smem_bytes = SMEM_FLOATS * sizeof(float);   // ~25.7 KB
    cudaFuncSetAttribute(nfm_fused_kernel,
                         cudaFuncAttributeMaxDynamicSharedMemorySize, smem_bytes);

    nfm_fused_kernel<<<BATCH / ROWS, THREADS, smem_bytes>>>(
        features, emb, bias_table, w_bias, W1, b1, W2, b2, Wp, bp, out);
}

// round 14
// speedup vs baseline: 1.7015x; 1.2860x over previous
#include <cuda_runtime.h>
#include <cstdint>

#define BATCH    16384
#define NFIELDS  50
#define DIM      64
#define L1DIM    128
#define L2DIM    64
#define ROWS     16      // batch rows per block
#define THREADS  128     // 4 warps, 4 rows per warp -> 8 blocks/SM at 64 regs

// dynamic shared layout (floats):
//   sFM   : ROWS*64   (reused as sH2 after h1 is computed)
//   sH1   : ROWS*128
//   sB1   : 128
//   sB2   : 64
//   sWp   : 64
//   sBias : ROWS
#define SMEM_FLOATS (ROWS*64 + ROWS*128 + 128 + 64 + 64 + ROWS)

__global__ __launch_bounds__(THREADS, 8)
void nfm_fused_kernel(const int*   __restrict__ features,
                      const float* __restrict__ emb,
                      const float* __restrict__ bias_table,
                      const float* __restrict__ w_bias,
                      const float* __restrict__ W1,
                      const float* __restrict__ b1,
                      const float* __restrict__ W2,
                      const float* __restrict__ b2,
                      const float* __restrict__ Wp,
                      const float* __restrict__ bp,
                      float*       __restrict__ out)
{
    extern __shared__ float sm[];
    float* sFM   = sm;                    // ROWS*64, reused as sH2
    float* sH1   = sFM  + ROWS*64;        // ROWS*128
    float* sB1   = sH1  + ROWS*128;       // 128
    float* sB2   = sB1  + 128;            // 64
    float* sWp   = sB2  + 64;             // 64
    float* sBias = sWp  + 64;             // ROWS
    float* sH2   = sFM;                   // overlay

    const int tid  = threadIdx.x;
    const int lane = tid & 31;
    const int wid  = tid >> 5;            // 0..3

    // ---- stage small params into shared ------------------------------------
    if (tid < 128) sB1[tid] = b1[tid];
    if (tid < 64)  sB2[tid] = b2[tid];
    else           sWp[tid - 64] = Wp[tid - 64];

    // ---- gather + FM bi-interaction -----------------------------------------
    // warp w owns rows 4w..4w+3 as two pairs. Within a pair: lanes 0-15 = row A,
    // lanes 16-31 = row B, each lane holds 4 dims (float4) -> ONE LDG.128 per
    // field serves both rows. Indices loaded uniformly (int2-vectorized, no
    // shfl in the address path) -> all embedding LDGs independent.
    const int row0 = blockIdx.x * ROWS;
    const int half = lane >> 4;          // 0 -> row A, 1 -> row B
    const int l16  = lane & 15;

    #pragma unroll
    for (int p = 0; p < 2; ++p) {
        const int rA = wid * 4 + p * 2;
        const int rB = rA + 1;
        const int2* frA = reinterpret_cast<const int2*>(
                              features + (long)(row0 + rA) * NFIELDS);
        const int2* frB = reinterpret_cast<const int2*>(
                              features + (long)(row0 + rB) * NFIELDS);

        float4 s  = make_float4(0.f, 0.f, 0.f, 0.f);
        float4 sq = make_float4(0.f, 0.f, 0.f, 0.f);
        float  bsA = 0.f, bsB = 0.f;

        #pragma unroll
        for (int f2 = 0; f2 < NFIELDS / 2; ++f2) {        // 25 int2 per row
            const int2 ia2 = __ldg(frA + f2);             // uniform
            const int2 ib2 = __ldg(frB + f2);             // uniform
            {
                const int idx = half ? ib2.x : ia2.x;
                const float4 v = *reinterpret_cast<const float4*>(
                                     emb + (long)idx * DIM + l16 * 4);
                bsA += __ldg(bias_table + ia2.x);
                bsB += __ldg(bias_table + ib2.x);
                s.x  += v.x;       s.y  += v.y;       s.z  += v.z;       s.w  += v.w;
                sq.x += v.x * v.x; sq.y += v.y * v.y; sq.z += v.z * v.z; sq.w += v.w * v.w;
            }
            {
                const int idx = half ? ib2.y : ia2.y;
                const float4 v = *reinterpret_cast<const float4*>(
                                     emb + (long)idx * DIM + l16 * 4);
                bsA += __ldg(bias_table + ia2.y);
                bsB += __ldg(bias_table + ib2.y);
                s.x  += v.x;       s.y  += v.y;       s.z  += v.z;       s.w  += v.w;
                sq.x += v.x * v.x; sq.y += v.y * v.y; sq.z += v.z * v.z; sq.w += v.w * v.w;
            }
        }
        float4 fm;
        fm.x = 0.5f * (s.x * s.x - sq.x);
        fm.y = 0.5f * (s.y * s.y - sq.y);
        fm.z = 0.5f * (s.z * s.z - sq.z);
        fm.w = 0.5f * (s.w * s.w - sq.w);
        const int rl = half ? rB : rA;
        *reinterpret_cast<float4*>(sFM + rl * DIM + l16 * 4) = fm;
        if (lane == 0) { sBias[rA] = bsA; sBias[rB] = bsB; }
    }
    __syncthreads();

    // ---- h1 = relu(FM @ W1 + b1)  [ROWS x 128], 4 rows/warp, float4 weights -
    {
        const int c4 = lane * 4;   // thread owns cols c4..c4+3
        const int r0 = wid * 4;    // 4 rows per warp
        float acc[4][4];
        #pragma unroll
        for (int i = 0; i < 4; ++i)
            #pragma unroll
            for (int k = 0; k < 4; ++k) acc[i][k] = sB1[c4 + k];

        #pragma unroll
        for (int d = 0; d < DIM; ++d) {
            const float4 w = __ldg(reinterpret_cast<const float4*>(
                                       W1 + d * L1DIM + c4));
            #pragma unroll
            for (int i = 0; i < 4; ++i) {
                const float fv = sFM[(r0 + i) * DIM + d];   // broadcast
                acc[i][0] += fv * w.x;  acc[i][1] += fv * w.y;
                acc[i][2] += fv * w.z;  acc[i][3] += fv * w.w;
            }
        }
        #pragma unroll
        for (int i = 0; i < 4; ++i) {
            float4 r;
            r.x = fmaxf(acc[i][0], 0.f);
            r.y = fmaxf(acc[i][1], 0.f);
            r.z = fmaxf(acc[i][2], 0.f);
            r.w = fmaxf(acc[i][3], 0.f);
            *reinterpret_cast<float4*>(sH1 + (r0 + i) * L1DIM + c4) = r;
        }
    }
    __syncthreads();   // sFM dead from here; safe to overlay sH2

    // ---- h2 = relu(H1 @ W2 + b2)  [ROWS x 64], 4 rows/warp, float2 weights --
    {
        const int c2 = lane * 2;   // thread owns cols c2, c2+1
        const int r0 = wid * 4;
        float acc[4][2];
        #pragma unroll
        for (int i = 0; i < 4; ++i) {
            acc[i][0] = sB2[c2];
            acc[i][1] = sB2[c2 + 1];
        }
        #pragma unroll
        for (int d = 0; d < L1DIM; ++d) {
            const float2 w = __ldg(reinterpret_cast<const float2*>(
                                       W2 + d * L2DIM + c2));
            #pragma unroll
            for (int i = 0; i < 4; ++i) {
                const float h = sH1[(r0 + i) * L1DIM + d];  // broadcast
                acc[i][0] += h * w.x;
                acc[i][1] += h * w.y;
            }
        }
        #pragma unroll
        for (int i = 0; i < 4; ++i) {
            float2 r;
            r.x = fmaxf(acc[i][0], 0.f);
            r.y = fmaxf(acc[i][1], 0.f);
            *reinterpret_cast<float2*>(sH2 + (r0 + i) * L2DIM + c2) = r;
        }
    }
    __syncthreads();

    // ---- pred = H2 @ Wp + bp, final sum ------------------------------------
    {
        const float gb  = __ldg(w_bias);
        const float bpv = __ldg(bp);
        #pragma unroll
        for (int i = 0; i < 4; ++i) {
            const int rl = wid * 4 + i;
            float v = sH2[rl * L2DIM + lane]      * sWp[lane]
                    + sH2[rl * L2DIM + lane + 32] * sWp[lane + 32];
            #pragma unroll
            for (int o = 16; o; o >>= 1) v += __shfl_down_sync(0xffffffffu, v, o);
            if (lane == 0) out[row0 + rl] = v + bpv + sBias[rl] + gb;
        }
    }
}

extern "C" void kernel_launch(void* const* d_in, const int* in_sizes, int n_in,
                              void* d_out, int out_size)
{
    const int*   features   = (const int*)  d_in[0];
    // d_in[1] = labels (unused, shape-only in reference)
    const float* emb        = (const float*)d_in[2];
    const float* bias_table = (const float*)d_in[3];
    const float* w_bias     = (const float*)d_in[4];
    const float* W1         = (const float*)d_in[5];
    const float* b1         = (const float*)d_in[6];
    const float* W2         = (const float*)d_in[7];
    const float* b2         = (const float*)d_in[8];
    const float* Wp         = (const float*)d_in[9];
    const float* bp         = (const float*)d_in[10];
    float*       out        = (float*)d_out;

    const int smem_bytes = SMEM_FLOATS * sizeof(float);   // ~13 KB
    cudaFuncSetAttribute(nfm_fused_kernel,
                         cudaFuncAttributeMaxDynamicSharedMemorySize, smem_bytes);

    nfm_fused_kernel<<<BATCH / ROWS, THREADS, smem_bytes>>>(
        features, emb, bias_table, w_bias, W1, b1, W2, b2, Wp, bp, out);
}